// round 12
// baseline (speedup 1.0000x reference)
#include <cuda_runtime.h>
#include <cuda_fp16.h>
#include <math.h>

#define BB 32
#define II 1024
#define CC 128
#define JJ 32
#define DD 64
#define JD 2048            // JJ*DD
#define NCH_R 32           // reduce chunks (init route)
#define ICH_R (II/NCH_R)   // 32 i's per reduce block
#define RCH 64             // route chunks
#define RICH (II/RCH)      // 16 i's per route block

// Scratch (device globals: no allocation in kernel_launch)
__device__ float g_uhat[(size_t)BB * II * JD];   // [b][i][j*64+d], 256 MiB
__device__ float g_spart[RCH][BB * JD];          // partial s sums, 16 MiB
__device__ float g_b1[(size_t)BB * II * JJ];     // routing logits after agree1
__device__ float g_v[BB * JD];                   // current v[b][j][d]

// ---------------------------------------------------------------------------
// fp16 mma helper (m16n8k16, fp32 accumulate)
// ---------------------------------------------------------------------------
__device__ __forceinline__ void mma_f16(float c[4],
                                        unsigned a0, unsigned a1, unsigned a2, unsigned a3,
                                        unsigned b0, unsigned b1) {
    asm volatile(
        "mma.sync.aligned.m16n8k16.row.col.f32.f16.f16.f32 "
        "{%0,%1,%2,%3}, {%4,%5,%6,%7}, {%8,%9}, {%0,%1,%2,%3};"
        : "+f"(c[0]), "+f"(c[1]), "+f"(c[2]), "+f"(c[3])
        : "r"(a0), "r"(a1), "r"(a2), "r"(a3), "r"(b0), "r"(b1));
}

__device__ __forceinline__ unsigned h2u(__half2 h) {
    return *reinterpret_cast<unsigned*>(&h);
}

// split float2 into fp16 hi + fp16 lo (Markidis), packed half2
__device__ __forceinline__ void split2(float2 w, unsigned& hi, unsigned& lo) {
    __half2 h = __floats2half2_rn(w.x, w.y);
    float2 r = make_float2(w.x - __low2float(h), w.y - __high2float(h));
    __half2 l = __floats2half2_rn(r.x, r.y);
    hi = h2u(h); lo = h2u(l);
}

// ---------------------------------------------------------------------------
// Kernel 1: u_hat GEMM, fp16x3 error-compensated (~fp32 accuracy).
// Block = (one i, 128-wide jd tile), 128 threads / 4 warps.
// Each warp OWNS a 32-row n-slice: it cp.async-copies its 16KB W slice
// (fully sequential, coalesced) into a padded smem stage, wait_group(0) +
// __syncwarp, then computes full K for that slice. This converts the W DRAM
// stream from 64B-scattered (r8-r11, capped ~5.0 TB/s) to dense sequential
// (reduce kernel measured 7.1 TB/s).
// k-PERMUTED fragments as before: W fragment = one LDS.128 (float4), A
// fragment = two contiguous LDS.64 from the split-fp16 x stage.
// ---------------------------------------------------------------------------
#define XS 144                 // half-stride per x row (conflict-free LDS.64)
#define WST 576                // padded W stage row stride (144 words = 16 mod 32)
#define STAGE_BYTES (32 * WST) // 18432 B per warp stage
#define X_BYTES (2 * 32 * XS * 2)                  // xh + xl = 18432 B
#define GEMM_SMEM (X_BYTES + 4 * STAGE_BYTES)      // 92160 B

__global__ void __launch_bounds__(128, 2)
gemm_kernel(const float* __restrict__ x, const float* __restrict__ W) {
    extern __shared__ char smem[];
    __half* xh = (__half*)smem;
    __half* xl = xh + 32 * XS;
    char*   ws = smem + X_BYTES;

    const int i    = blockIdx.y;
    const int jt   = blockIdx.x;          // 0..15 -> jd base = jt*128
    const int tid  = threadIdx.x;
    const int lane = tid & 31;
    const int warp = tid >> 5;            // 0..3, owns n slice warp*32..+31

    // 1) warp stages its 16KB W slice (rows = 32 consecutive n, contiguous gmem)
    {
        const int j  = jt * 2 + (warp >> 1);
        const int d0 = (warp & 1) * 32;
        const char* src = (const char*)(W + (((size_t)j * II + i) * DD + d0) * CC);
        char* dst = ws + warp * STAGE_BYTES;
        unsigned dstu = (unsigned)__cvta_generic_to_shared(dst) + lane * 16;
        size_t   srcg = (size_t)__cvta_generic_to_global(src) + lane * 16;
#pragma unroll
        for (int k = 0; k < 32; k++) {
            asm volatile("cp.async.cg.shared.global [%0], [%1], 16;"
                         :: "r"(dstu + k * WST), "l"(srcg + k * 512));
        }
        asm volatile("cp.async.commit_group;");
    }

    // 2) stage x[:, i, :] split into fp16 hi/lo, row-major [b][c]
    for (int e = tid * 4; e < BB * CC; e += 512) {
        int b = e >> 7, c = e & 127;
        float4 v = *(const float4*)(x + ((size_t)b * II + i) * CC + c);
        float f[4] = {v.x, v.y, v.z, v.w};
#pragma unroll
        for (int k = 0; k < 4; k++) {
            __half h = __float2half_rn(f[k]);
            xh[b * XS + c + k] = h;
            xl[b * XS + c + k] = __float2half_rn(f[k] - __half2float(h));
        }
    }
    __syncthreads();

    // 3) wait for this warp's own stage (one group per warp), make it visible
    asm volatile("cp.async.wait_group 0;" ::: "memory");
    __syncwarp();

    const char* sw = ws + warp * STAGE_BYTES;
    const int arow = lane >> 2;
    const int acol = lane & 3;
    const int rbase = (lane >> 2) * WST + acol * 16;   // per-lane row/col offset

    float acc[2][4][4] = {};

#pragma unroll
    for (int s = 0; s < 8; s++) {          // K = 8 steps of 16 (physical 16 c's)
        // W fragments: one LDS.128 per q, conflict-free (WST = 16 words mod 32)
        unsigned bh[4][2], bl[4][2];
#pragma unroll
        for (int q = 0; q < 4; q++) {
            float4 wv = *(const float4*)(sw + q * 8 * WST + rbase + s * 64);
            split2(make_float2(wv.x, wv.y), bh[q][0], bl[q][0]);
            split2(make_float2(wv.z, wv.w), bh[q][1], bl[q][1]);
        }
        // A fragments: a0|a2 contiguous (8B), a1|a3 contiguous (8B), hi and lo
        unsigned ah[2][4], al[2][4];
#pragma unroll
        for (int mt = 0; mt < 2; mt++) {
            const int base = (mt * 16 + arow) * XS + s * 16 + acol * 4;
            uint2 h0 = *(const uint2*)(xh + base);
            uint2 h1 = *(const uint2*)(xh + base + 8 * XS);
            uint2 l0 = *(const uint2*)(xl + base);
            uint2 l1 = *(const uint2*)(xl + base + 8 * XS);
            ah[mt][0] = h0.x; ah[mt][2] = h0.y;
            ah[mt][1] = h1.x; ah[mt][3] = h1.y;
            al[mt][0] = l0.x; al[mt][2] = l0.y;
            al[mt][1] = l1.x; al[mt][3] = l1.y;
        }
#pragma unroll
        for (int q = 0; q < 4; q++) {
#pragma unroll
            for (int mt = 0; mt < 2; mt++) {
                mma_f16(acc[mt][q], ah[mt][0], ah[mt][1], ah[mt][2], ah[mt][3],
                        bl[q][0], bl[q][1]);
                mma_f16(acc[mt][q], al[mt][0], al[mt][1], al[mt][2], al[mt][3],
                        bh[q][0], bh[q][1]);
                mma_f16(acc[mt][q], ah[mt][0], ah[mt][1], ah[mt][2], ah[mt][3],
                        bh[q][0], bh[q][1]);
            }
        }
    }

    // Epilogue: u_hat fp32, [b][i][jd]; float2 stores (cols 2t,2t+1 contiguous)
    const int nb = jt * 128 + warp * 32;
#pragma unroll
    for (int mt = 0; mt < 2; mt++) {
        int b0r = mt * 16 + (lane >> 2);
#pragma unroll
        for (int q = 0; q < 4; q++) {
            int col = nb + q * 8 + 2 * (lane & 3);
            *(float2*)(g_uhat + ((size_t)b0r * II + i) * JD + col) =
                make_float2(acc[mt][q][0], acc[mt][q][1]);
            *(float2*)(g_uhat + ((size_t)(b0r + 8) * II + i) * JD + col) =
                make_float2(acc[mt][q][2], acc[mt][q][3]);
        }
    }
}

// ---------------------------------------------------------------------------
// Kernel 2: partial sums over i of u_hat (route-1: c = 1/J uniform).
// ---------------------------------------------------------------------------
__global__ void reduce_uhat_kernel() {
    int idx = blockIdx.x * 256 + threadIdx.x;   // 0..16383 = b*512 + jd/4
    int ch  = blockIdx.y;
    int b   = idx >> 9, jd4 = idx & 511;
    const float4* p = (const float4*)(g_uhat + ((size_t)b * II + ch * ICH_R) * JD) + jd4;
    float4 s = make_float4(0.f, 0.f, 0.f, 0.f);
#pragma unroll 8
    for (int k = 0; k < ICH_R; k++) {
        float4 u = p[(size_t)k * (JD / 4)];
        s.x += u.x; s.y += u.y; s.z += u.z; s.w += u.w;
    }
    *(float4*)(&g_spart[ch][b * JD + jd4 * 4]) = s;
}

// ---------------------------------------------------------------------------
// Kernel 3: reduce partials + squash.  out==nullptr -> write g_v.
// ---------------------------------------------------------------------------
__global__ void __launch_bounds__(256)
squash_kernel(float scale, float* out, int nchunk) {
    const int tid  = threadIdx.x;
    const int bjd  = blockIdx.x * 256 + tid;    // global (bj*64 + d)
    const int lane = tid & 31;
    const int warp = tid >> 5;
    const int grp  = tid >> 6;                  // 0..3: (b,j) group in block

    float s = 0.f;
#pragma unroll 8
    for (int ch = 0; ch < nchunk; ch++) s += g_spart[ch][bjd];
    s *= scale;

    float n2 = s * s;
#pragma unroll
    for (int off = 16; off; off >>= 1) n2 += __shfl_xor_sync(0xffffffffu, n2, off);
    __shared__ float tmp[8];
    if (lane == 0) tmp[warp] = n2;
    __syncthreads();
    n2 = tmp[2 * grp] + tmp[2 * grp + 1];

    float norm = sqrtf(n2);
    float f    = norm / (1.f + n2);
    float* dst = out ? out : g_v;
    dst[bjd] = s * f;
}

// ---------------------------------------------------------------------------
// Kernel 4: fused agree + next-route partial-sum, register-resident,
// 2-way i-unroll, dual softmax (lanes 0-15: i0, lanes 16-31: i1).
// One __syncthreads per pair, 4-slot logit ring.
// ---------------------------------------------------------------------------
template <bool FIRST>
__global__ void __launch_bounds__(256)
route_kernel() {
    __shared__ float bj_s[4][JJ];

    const int b    = blockIdx.x;
    const int ch   = blockIdx.y;
    const int tid  = threadIdx.x;
    const int lane = tid & 31;
    const int j    = tid >> 3;        // 0..31
    const int d0   = (tid & 7) * 8;
    const int hl   = lane & 15;       // position within 16-lane half

    float v[8];
#pragma unroll
    for (int k = 0; k < 8; k++) v[k] = g_v[b * JD + j * 64 + d0 + k];

    const float* ub = g_uhat + ((size_t)b * II + ch * RICH) * JD + j * 64 + d0;
    const float* bb = g_b1 + ((size_t)b * II + ch * RICH) * JJ + j;
    float* bw       = g_b1 + ((size_t)b * II + ch * RICH) * JJ + j;

    float sacc[8] = {};
    float u[2][8];
    float b1v[2];

    // prologue: load t = 0, 1
#pragma unroll
    for (int r = 0; r < 2; r++) {
        float4 a = *(const float4*)(ub + (size_t)r * JD);
        float4 c = *(const float4*)(ub + (size_t)r * JD + 4);
        u[r][0]=a.x; u[r][1]=a.y; u[r][2]=a.z; u[r][3]=a.w;
        u[r][4]=c.x; u[r][5]=c.y; u[r][6]=c.z; u[r][7]=c.w;
        b1v[r] = FIRST ? 0.f : bb[(size_t)r * JJ];
    }

#pragma unroll
    for (int p = 0; p < RICH / 2; p++) {
        // agreement dots for both i's of this pair
#pragma unroll
        for (int r = 0; r < 2; r++) {
            const int t = 2 * p + r;
            float dot = 0.f;
#pragma unroll
            for (int k = 0; k < 8; k++) dot = fmaf(u[r][k], v[k], dot);
            dot += __shfl_xor_sync(0xffffffffu, dot, 1);
            dot += __shfl_xor_sync(0xffffffffu, dot, 2);
            dot += __shfl_xor_sync(0xffffffffu, dot, 4);
            if ((lane & 7) == 0) {
                if (FIRST) bw[(size_t)t * JJ] = dot;   // b starts at 0
                bj_s[t & 3][j] = dot + b1v[r];
            }
        }
        __syncthreads();

        // prefetch next pair (overlaps the softmax chain below)
        float un[2][8];
        float b1n[2];
        if (p + 1 < RICH / 2) {
#pragma unroll
            for (int r = 0; r < 2; r++) {
                const size_t t = 2 * p + 2 + r;
                float4 a = *(const float4*)(ub + t * JD);
                float4 c = *(const float4*)(ub + t * JD + 4);
                un[r][0]=a.x; un[r][1]=a.y; un[r][2]=a.z; un[r][3]=a.w;
                un[r][4]=c.x; un[r][5]=c.y; un[r][6]=c.z; un[r][7]=c.w;
                b1n[r] = FIRST ? 0.f : bb[t * JJ];
            }
        }

        // dual softmax: half 0 (lanes 0-15) does i=2p, half 1 does i=2p+1
        {
            const int half = lane >> 4;
            const int slot = (2 * p + half) & 3;
            float x0 = bj_s[slot][hl];
            float x1 = bj_s[slot][hl + 16];
            float m = fmaxf(x0, x1);
#pragma unroll
            for (int off = 8; off; off >>= 1)
                m = fmaxf(m, __shfl_xor_sync(0xffffffffu, m, off));
            float e0 = __expf(x0 - m);
            float e1 = __expf(x1 - m);
            float ss = e0 + e1;
#pragma unroll
            for (int off = 8; off; off >>= 1)
                ss += __shfl_xor_sync(0xffffffffu, ss, off);
            float inv = __frcp_rn(ss);
            float r0 = e0 * inv;     // c for j = hl      (this half's i)
            float r1 = e1 * inv;     // c for j = hl + 16 (this half's i)

            // broadcast: c for (i0, j) lives in lane (j&15); (i1, j) in 16+(j&15)
            int js = j & 15;
            float a0 = __shfl_sync(0xffffffffu, r0, js);
            float a1 = __shfl_sync(0xffffffffu, r1, js);
            float c0 = (j < 16) ? a0 : a1;
            float b0 = __shfl_sync(0xffffffffu, r0, 16 + js);
            float b1x = __shfl_sync(0xffffffffu, r1, 16 + js);
            float c1 = (j < 16) ? b0 : b1x;

#pragma unroll
            for (int k = 0; k < 8; k++) sacc[k] = fmaf(c0, u[0][k], sacc[k]);
#pragma unroll
            for (int k = 0; k < 8; k++) sacc[k] = fmaf(c1, u[1][k], sacc[k]);
        }

        if (p + 1 < RICH / 2) {
#pragma unroll
            for (int r = 0; r < 2; r++) {
#pragma unroll
                for (int k = 0; k < 8; k++) u[r][k] = un[r][k];
                b1v[r] = b1n[r];
            }
        }
    }

    float* sp = &g_spart[ch][b * JD + tid * 8];
    *(float4*)(sp)     = make_float4(sacc[0], sacc[1], sacc[2], sacc[3]);
    *(float4*)(sp + 4) = make_float4(sacc[4], sacc[5], sacc[6], sacc[7]);
}

// ---------------------------------------------------------------------------
extern "C" void kernel_launch(void* const* d_in, const int* in_sizes, int n_in,
                              void* d_out, int out_size) {
    const float *x, *W;
    if (in_sizes[0] == BB * II * CC) { x = (const float*)d_in[0]; W = (const float*)d_in[1]; }
    else                             { x = (const float*)d_in[1]; W = (const float*)d_in[0]; }
    float* out = (float*)d_out;

    cudaFuncSetAttribute(gemm_kernel, cudaFuncAttributeMaxDynamicSharedMemorySize,
                         (int)GEMM_SMEM);

    // 1) u_hat GEMM (fp16x3 MMA, cp.async-staged sequential W streams)
    gemm_kernel<<<dim3(16, II), 128, GEMM_SMEM>>>(x, W);
    // 2) s1 = sum_i u_hat (partials), v1 = squash(s1 / J)
    reduce_uhat_kernel<<<dim3(BB * JD / 4 / 256, NCH_R), 256>>>();
    squash_kernel<<<BB * JJ / 4, 256>>>(1.0f / (float)JJ, nullptr, NCH_R);
    // 3) agree1 + route2 partials; v2 = squash(s2)
    route_kernel<true><<<dim3(BB, RCH), 256>>>();
    squash_kernel<<<BB * JJ / 4, 256>>>(1.0f, nullptr, RCH);
    // 4) agree2 + route3 partials; output = squash(s3)
    route_kernel<false><<<dim3(BB, RCH), 256>>>();
    squash_kernel<<<BB * JJ / 4, 256>>>(1.0f, out, RCH);
}

// round 14
// speedup vs baseline: 1.6225x; 1.6225x over previous
#include <cuda_runtime.h>
#include <cuda_fp16.h>
#include <math.h>

#define BB 32
#define II 1024
#define CC 128
#define JJ 32
#define DD 64
#define JD 2048            // JJ*DD
#define NCH_R 32           // reduce chunks (init route)
#define ICH_R (II/NCH_R)   // 32 i's per reduce block
#define RCH 64             // route chunks
#define RICH (II/RCH)      // 16 i's per route block

#define QS   256.0f        // quantization scale: q = round(u * 256)
#define QSI  (1.0f/256.0f) // decode scale

// Scratch (device globals: no allocation in kernel_launch)
__device__ short g_uhat[(size_t)BB * II * JD];   // int16 q-units, 134 MiB
__device__ float g_spart[RCH][BB * JD];          // partial s sums, fp32
__device__ float g_b1[(size_t)BB * II * JJ];     // routing logits after agree1
__device__ float g_v[BB * JD];                   // current v[b][j][d]

// ---------------------------------------------------------------------------
// fp16 mma helper (m16n8k16, fp32 accumulate)
// ---------------------------------------------------------------------------
__device__ __forceinline__ void mma_f16(float c[4],
                                        unsigned a0, unsigned a1, unsigned a2, unsigned a3,
                                        unsigned b0, unsigned b1) {
    asm volatile(
        "mma.sync.aligned.m16n8k16.row.col.f32.f16.f16.f32 "
        "{%0,%1,%2,%3}, {%4,%5,%6,%7}, {%8,%9}, {%0,%1,%2,%3};"
        : "+f"(c[0]), "+f"(c[1]), "+f"(c[2]), "+f"(c[3])
        : "r"(a0), "r"(a1), "r"(a2), "r"(a3), "r"(b0), "r"(b1));
}

__device__ __forceinline__ unsigned h2u(__half2 h) {
    return *reinterpret_cast<unsigned*>(&h);
}

// split float2 into fp16 hi + fp16 lo (Markidis), packed half2
__device__ __forceinline__ void split2(float2 w, unsigned& hi, unsigned& lo) {
    __half2 h = __floats2half2_rn(w.x, w.y);
    float2 r = make_float2(w.x - __low2float(h), w.y - __high2float(h));
    __half2 l = __floats2half2_rn(r.x, r.y);
    hi = h2u(h); lo = h2u(l);
}

// unpack one uint (2 int16) to two floats in real units (q * QSI)
__device__ __forceinline__ void unpk(unsigned w, float& f0, float& f1) {
    f0 = (float)((short)(w & 0xFFFFu)) * QSI;
    f1 = (float)((short)(w >> 16))     * QSI;
}

// ---------------------------------------------------------------------------
// Kernel 1: u_hat GEMM, fp16x3 error-compensated (~fp32 accuracy), int16 out.
// Per block: one i, 128-wide jd tile (16 jd per warp), all 32 b. (r11 base —
// best measured decomposition.) k-PERMUTED fragments; W = LDG.128 read-once,
// depth-3 prefetch; A fragments = contiguous LDS.64 pairs.
// ---------------------------------------------------------------------------
#define XS 144   // half-stride per row (72 words = 8 mod 32: conflict-free LDS.64)

__global__ void __launch_bounds__(256, 3)
gemm_kernel(const float* __restrict__ x, const float* __restrict__ W) {
    __shared__ __half xh[32 * XS];
    __shared__ __half xl[32 * XS];

    const int i    = blockIdx.y;
    const int jt   = blockIdx.x;          // 0..15 -> jd base = jt*128
    const int tid  = threadIdx.x;
    const int lane = tid & 31;
    const int warp = tid >> 5;

    // Stage x[:, i, :] split into fp16 hi/lo, row-major [b][c] (physical c order)
    for (int e = tid * 4; e < BB * CC; e += 1024) {
        int b = e >> 7, c = e & 127;
        float4 v = *(const float4*)(x + ((size_t)b * II + i) * CC + c);
        float f[4] = {v.x, v.y, v.z, v.w};
#pragma unroll
        for (int k = 0; k < 4; k++) {
            __half h = __float2half_rn(f[k]);
            xh[b * XS + c + k] = h;
            xl[b * XS + c + k] = __float2half_rn(f[k] - __half2float(h));
        }
    }
    __syncthreads();

    const int nbase = jt * 128 + warp * 16;   // this warp's jd base (16 wide)
    const float4* Wp[2];
#pragma unroll
    for (int q = 0; q < 2; q++) {
        int n = nbase + q * 8 + (lane >> 2);
        int j = n >> 6, d = n & 63;
        Wp[q] = (const float4*)(W + (((size_t)j * II + i) * DD + d) * CC) + (lane & 3);
    }

    float acc[2][2][4] = {};
    float4 bf[3][2];   // depth-3 prefetch: [step mod 3][q]

    // prologue: steps 0, 1, 2
#pragma unroll
    for (int g = 0; g < 3; g++)
#pragma unroll
        for (int q = 0; q < 2; q++) bf[g][q] = Wp[q][g * 4];

    const int arow = lane >> 2;
    const int acol = lane & 3;

#pragma unroll
    for (int s = 0; s < 8; s++) {          // K = 8 steps of 16
        const int cur = s % 3;
        unsigned bh[2][2], bl[2][2];
#pragma unroll
        for (int q = 0; q < 2; q++) {
            split2(make_float2(bf[cur][q].x, bf[cur][q].y), bh[q][0], bl[q][0]);
            split2(make_float2(bf[cur][q].z, bf[cur][q].w), bh[q][1], bl[q][1]);
        }
        if (s < 5) {
#pragma unroll
            for (int q = 0; q < 2; q++) bf[cur][q] = Wp[q][(s + 3) * 4];
        }
        unsigned ah[2][4], al[2][4];
#pragma unroll
        for (int mt = 0; mt < 2; mt++) {
            const int base = (mt * 16 + arow) * XS + s * 16 + acol * 4;
            uint2 h0 = *(const uint2*)(xh + base);
            uint2 h1 = *(const uint2*)(xh + base + 8 * XS);
            uint2 l0 = *(const uint2*)(xl + base);
            uint2 l1 = *(const uint2*)(xl + base + 8 * XS);
            ah[mt][0] = h0.x; ah[mt][2] = h0.y;
            ah[mt][1] = h1.x; ah[mt][3] = h1.y;
            al[mt][0] = l0.x; al[mt][2] = l0.y;
            al[mt][1] = l1.x; al[mt][3] = l1.y;
        }
#pragma unroll
        for (int q = 0; q < 2; q++) {
#pragma unroll
            for (int mt = 0; mt < 2; mt++) {
                mma_f16(acc[mt][q], ah[mt][0], ah[mt][1], ah[mt][2], ah[mt][3],
                        bl[q][0], bl[q][1]);
                mma_f16(acc[mt][q], al[mt][0], al[mt][1], al[mt][2], al[mt][3],
                        bh[q][0], bh[q][1]);
                mma_f16(acc[mt][q], ah[mt][0], ah[mt][1], ah[mt][2], ah[mt][3],
                        bh[q][0], bh[q][1]);
            }
        }
    }

    // Epilogue: u_hat int16 (q = round(u*256)); short2 stores, 2 cols contiguous
#pragma unroll
    for (int mt = 0; mt < 2; mt++) {
        int b0r = mt * 16 + (lane >> 2);
#pragma unroll
        for (int q = 0; q < 2; q++) {
            int col = nbase + q * 8 + 2 * (lane & 3);
            short2 s01 = make_short2((short)__float2int_rn(acc[mt][q][0] * QS),
                                     (short)__float2int_rn(acc[mt][q][1] * QS));
            short2 s23 = make_short2((short)__float2int_rn(acc[mt][q][2] * QS),
                                     (short)__float2int_rn(acc[mt][q][3] * QS));
            *(short2*)(g_uhat + ((size_t)b0r * II + i) * JD + col)       = s01;
            *(short2*)(g_uhat + ((size_t)(b0r + 8) * II + i) * JD + col) = s23;
        }
    }
}

// ---------------------------------------------------------------------------
// Kernel 2: partial sums over i of u_hat (route-1: c = 1/J uniform).
// int32 accumulation: BIT-EXACT sum of int16 q-values (max 32*2^15 < 2^31).
// Thread handles 8 consecutive shorts (one uint4 / 16B per i).
// ---------------------------------------------------------------------------
__global__ void reduce_uhat_kernel() {
    int idx = blockIdx.x * 256 + threadIdx.x;   // 0..8191 = b*256 + g
    int ch  = blockIdx.y;
    int b   = idx >> 8, g = idx & 255;          // g: 8-short group within row
    const uint4* p = (const uint4*)(g_uhat + ((size_t)b * II + ch * ICH_R) * JD) + g;
    int acc[8] = {};
#pragma unroll 8
    for (int k = 0; k < ICH_R; k++) {
        uint4 raw = p[(size_t)k * (JD / 8)];
        unsigned w[4] = {raw.x, raw.y, raw.z, raw.w};
#pragma unroll
        for (int m = 0; m < 4; m++) {
            acc[2 * m]     += (int)((short)(w[m] & 0xFFFFu));
            acc[2 * m + 1] += (int)((short)(w[m] >> 16));
        }
    }
    float* sp = &g_spart[ch][b * JD + g * 8];
    *(float4*)(sp)     = make_float4(acc[0] * QSI, acc[1] * QSI, acc[2] * QSI, acc[3] * QSI);
    *(float4*)(sp + 4) = make_float4(acc[4] * QSI, acc[5] * QSI, acc[6] * QSI, acc[7] * QSI);
}

// ---------------------------------------------------------------------------
// Kernel 3: reduce partials + squash.  out==nullptr -> write g_v.
// ---------------------------------------------------------------------------
__global__ void __launch_bounds__(256)
squash_kernel(float scale, float* out, int nchunk) {
    const int tid  = threadIdx.x;
    const int bjd  = blockIdx.x * 256 + tid;    // global (bj*64 + d)
    const int lane = tid & 31;
    const int warp = tid >> 5;
    const int grp  = tid >> 6;                  // 0..3: (b,j) group in block

    float s = 0.f;
#pragma unroll 8
    for (int ch = 0; ch < nchunk; ch++) s += g_spart[ch][bjd];
    s *= scale;

    float n2 = s * s;
#pragma unroll
    for (int off = 16; off; off >>= 1) n2 += __shfl_xor_sync(0xffffffffu, n2, off);
    __shared__ float tmp[8];
    if (lane == 0) tmp[warp] = n2;
    __syncthreads();
    n2 = tmp[2 * grp] + tmp[2 * grp + 1];

    float norm = sqrtf(n2);
    float f    = norm / (1.f + n2);
    float* dst = out ? out : g_v;
    dst[bjd] = s * f;
}

// ---------------------------------------------------------------------------
// Kernel 4: fused agree + next-route partial-sum, register-resident,
// 2-way i-unroll, dual softmax (lanes 0-15: i0, lanes 16-31: i1).
// u is int16: ONE LDG.128 (8 shorts) per thread per i, decoded to fp32.
// One __syncthreads per pair, 4-slot logit ring.
// ---------------------------------------------------------------------------
template <bool FIRST>
__global__ void __launch_bounds__(256)
route_kernel() {
    __shared__ float bj_s[4][JJ];

    const int b    = blockIdx.x;
    const int ch   = blockIdx.y;
    const int tid  = threadIdx.x;
    const int lane = tid & 31;
    const int j    = tid >> 3;        // 0..31
    const int d0   = (tid & 7) * 8;
    const int hl   = lane & 15;       // position within 16-lane half

    float v[8];
#pragma unroll
    for (int k = 0; k < 8; k++) v[k] = g_v[b * JD + j * 64 + d0 + k];

    const short* ub = g_uhat + ((size_t)b * II + ch * RICH) * JD + j * 64 + d0;
    const float* bb = g_b1 + ((size_t)b * II + ch * RICH) * JJ + j;
    float* bw       = g_b1 + ((size_t)b * II + ch * RICH) * JJ + j;

    float sacc[8] = {};
    float u[2][8];
    float b1v[2];

    // prologue: load t = 0, 1
#pragma unroll
    for (int r = 0; r < 2; r++) {
        uint4 raw = *(const uint4*)(ub + (size_t)r * JD);
        unpk(raw.x, u[r][0], u[r][1]);
        unpk(raw.y, u[r][2], u[r][3]);
        unpk(raw.z, u[r][4], u[r][5]);
        unpk(raw.w, u[r][6], u[r][7]);
        b1v[r] = FIRST ? 0.f : bb[(size_t)r * JJ];
    }

#pragma unroll
    for (int p = 0; p < RICH / 2; p++) {
        // agreement dots for both i's of this pair
#pragma unroll
        for (int r = 0; r < 2; r++) {
            const int t = 2 * p + r;
            float dot = 0.f;
#pragma unroll
            for (int k = 0; k < 8; k++) dot = fmaf(u[r][k], v[k], dot);
            dot += __shfl_xor_sync(0xffffffffu, dot, 1);
            dot += __shfl_xor_sync(0xffffffffu, dot, 2);
            dot += __shfl_xor_sync(0xffffffffu, dot, 4);
            if ((lane & 7) == 0) {
                if (FIRST) bw[(size_t)t * JJ] = dot;   // b starts at 0
                bj_s[t & 3][j] = dot + b1v[r];
            }
        }
        __syncthreads();

        // prefetch next pair (overlaps the softmax chain below)
        float un[2][8];
        float b1n[2];
        if (p + 1 < RICH / 2) {
#pragma unroll
            for (int r = 0; r < 2; r++) {
                const size_t t = 2 * p + 2 + r;
                uint4 raw = *(const uint4*)(ub + t * JD);
                unpk(raw.x, un[r][0], un[r][1]);
                unpk(raw.y, un[r][2], un[r][3]);
                unpk(raw.z, un[r][4], un[r][5]);
                unpk(raw.w, un[r][6], un[r][7]);
                b1n[r] = FIRST ? 0.f : bb[t * JJ];
            }
        }

        // dual softmax: half 0 (lanes 0-15) does i=2p, half 1 does i=2p+1
        {
            const int half = lane >> 4;
            const int slot = (2 * p + half) & 3;
            float x0 = bj_s[slot][hl];
            float x1 = bj_s[slot][hl + 16];
            float m = fmaxf(x0, x1);
#pragma unroll
            for (int off = 8; off; off >>= 1)
                m = fmaxf(m, __shfl_xor_sync(0xffffffffu, m, off));
            float e0 = __expf(x0 - m);
            float e1 = __expf(x1 - m);
            float ss = e0 + e1;
#pragma unroll
            for (int off = 8; off; off >>= 1)
                ss += __shfl_xor_sync(0xffffffffu, ss, off);
            float inv = __frcp_rn(ss);
            float r0 = e0 * inv;     // c for j = hl      (this half's i)
            float r1 = e1 * inv;     // c for j = hl + 16 (this half's i)

            // broadcast: c for (i0, j) lives in lane (j&15); (i1, j) in 16+(j&15)
            int js = j & 15;
            float a0 = __shfl_sync(0xffffffffu, r0, js);
            float a1 = __shfl_sync(0xffffffffu, r1, js);
            float c0 = (j < 16) ? a0 : a1;
            float b0 = __shfl_sync(0xffffffffu, r0, 16 + js);
            float b1x = __shfl_sync(0xffffffffu, r1, 16 + js);
            float c1 = (j < 16) ? b0 : b1x;

#pragma unroll
            for (int k = 0; k < 8; k++) sacc[k] = fmaf(c0, u[0][k], sacc[k]);
#pragma unroll
            for (int k = 0; k < 8; k++) sacc[k] = fmaf(c1, u[1][k], sacc[k]);
        }

        if (p + 1 < RICH / 2) {
#pragma unroll
            for (int r = 0; r < 2; r++) {
#pragma unroll
                for (int k = 0; k < 8; k++) u[r][k] = un[r][k];
                b1v[r] = b1n[r];
            }
        }
    }

    float* sp = &g_spart[ch][b * JD + tid * 8];
    *(float4*)(sp)     = make_float4(sacc[0], sacc[1], sacc[2], sacc[3]);
    *(float4*)(sp + 4) = make_float4(sacc[4], sacc[5], sacc[6], sacc[7]);
}

// ---------------------------------------------------------------------------
extern "C" void kernel_launch(void* const* d_in, const int* in_sizes, int n_in,
                              void* d_out, int out_size) {
    const float *x, *W;
    if (in_sizes[0] == BB * II * CC) { x = (const float*)d_in[0]; W = (const float*)d_in[1]; }
    else                             { x = (const float*)d_in[1]; W = (const float*)d_in[0]; }
    float* out = (float*)d_out;

    // 1) u_hat GEMM (fp16x3 MMA, fp32-accurate, int16 u_hat output)
    gemm_kernel<<<dim3(16, II), 256>>>(x, W);
    // 2) s1 = sum_i u_hat (bit-exact int32 partials), v1 = squash(s1 / J)
    reduce_uhat_kernel<<<dim3(BB * JD / 8 / 256, NCH_R), 256>>>();
    squash_kernel<<<BB * JJ / 4, 256>>>(1.0f / (float)JJ, nullptr, NCH_R);
    // 3) agree1 + route2 partials; v2 = squash(s2)
    route_kernel<true><<<dim3(BB, RCH), 256>>>();
    squash_kernel<<<BB * JJ / 4, 256>>>(1.0f, nullptr, RCH);
    // 4) agree2 + route3 partials; output = squash(s3)
    route_kernel<false><<<dim3(BB, RCH), 256>>>();
    squash_kernel<<<BB * JJ / 4, 256>>>(1.0f, out, RCH);
}

// round 15
// speedup vs baseline: 1.6649x; 1.0262x over previous
#include <cuda_runtime.h>
#include <cuda_fp16.h>
#include <math.h>

#define BB 32
#define II 1024
#define CC 128
#define JJ 32
#define DD 64
#define JD 2048            // JJ*DD
#define NCH_R 32           // reduce chunks (init route)
#define ICH_R (II/NCH_R)   // 32 i's per reduce block
#define RCH 64             // route chunks
#define RICH (II/RCH)      // 16 i's per route block (8 pairs)

#define QS   256.0f        // quantization scale: q = round(u * 256)
#define QSI  (1.0f/256.0f) // decode scale

// Scratch (device globals: no allocation in kernel_launch)
__device__ short g_uhat[(size_t)BB * II * JD];   // int16 q-units, 134 MiB
__device__ float g_spart[RCH][BB * JD];          // partial s sums, fp32
__device__ float g_b1[(size_t)BB * II * JJ];     // routing logits after agree1
__device__ float g_v[BB * JD];                   // current v[b][j][d]

// ---------------------------------------------------------------------------
// fp16 mma helper (m16n8k16, fp32 accumulate)
// ---------------------------------------------------------------------------
__device__ __forceinline__ void mma_f16(float c[4],
                                        unsigned a0, unsigned a1, unsigned a2, unsigned a3,
                                        unsigned b0, unsigned b1) {
    asm volatile(
        "mma.sync.aligned.m16n8k16.row.col.f32.f16.f16.f32 "
        "{%0,%1,%2,%3}, {%4,%5,%6,%7}, {%8,%9}, {%0,%1,%2,%3};"
        : "+f"(c[0]), "+f"(c[1]), "+f"(c[2]), "+f"(c[3])
        : "r"(a0), "r"(a1), "r"(a2), "r"(a3), "r"(b0), "r"(b1));
}

__device__ __forceinline__ unsigned h2u(__half2 h) {
    return *reinterpret_cast<unsigned*>(&h);
}

// split float2 into fp16 hi + fp16 lo (Markidis), packed half2
__device__ __forceinline__ void split2(float2 w, unsigned& hi, unsigned& lo) {
    __half2 h = __floats2half2_rn(w.x, w.y);
    float2 r = make_float2(w.x - __low2float(h), w.y - __high2float(h));
    __half2 l = __floats2half2_rn(r.x, r.y);
    hi = h2u(h); lo = h2u(l);
}

// unpack one uint (2 int16) to two floats in real units (q * QSI)
__device__ __forceinline__ void unpk(unsigned w, float& f0, float& f1) {
    f0 = (float)((short)(w & 0xFFFFu)) * QSI;
    f1 = (float)((short)(w >> 16))     * QSI;
}

// ---------------------------------------------------------------------------
// Kernel 1: u_hat GEMM, fp16x3 error-compensated (~fp32 accuracy), int16 out.
// (r11/r14 base — best measured decomposition.)
// ---------------------------------------------------------------------------
#define XS 144   // half-stride per row (72 words = 8 mod 32: conflict-free LDS.64)

__global__ void __launch_bounds__(256, 3)
gemm_kernel(const float* __restrict__ x, const float* __restrict__ W) {
    __shared__ __half xh[32 * XS];
    __shared__ __half xl[32 * XS];

    const int i    = blockIdx.y;
    const int jt   = blockIdx.x;          // 0..15 -> jd base = jt*128
    const int tid  = threadIdx.x;
    const int lane = tid & 31;
    const int warp = tid >> 5;

    // Stage x[:, i, :] split into fp16 hi/lo, row-major [b][c] (physical c order)
    for (int e = tid * 4; e < BB * CC; e += 1024) {
        int b = e >> 7, c = e & 127;
        float4 v = *(const float4*)(x + ((size_t)b * II + i) * CC + c);
        float f[4] = {v.x, v.y, v.z, v.w};
#pragma unroll
        for (int k = 0; k < 4; k++) {
            __half h = __float2half_rn(f[k]);
            xh[b * XS + c + k] = h;
            xl[b * XS + c + k] = __float2half_rn(f[k] - __half2float(h));
        }
    }
    __syncthreads();

    const int nbase = jt * 128 + warp * 16;   // this warp's jd base (16 wide)
    const float4* Wp[2];
#pragma unroll
    for (int q = 0; q < 2; q++) {
        int n = nbase + q * 8 + (lane >> 2);
        int j = n >> 6, d = n & 63;
        Wp[q] = (const float4*)(W + (((size_t)j * II + i) * DD + d) * CC) + (lane & 3);
    }

    float acc[2][2][4] = {};
    float4 bf[3][2];   // depth-3 prefetch: [step mod 3][q]

    // prologue: steps 0, 1, 2
#pragma unroll
    for (int g = 0; g < 3; g++)
#pragma unroll
        for (int q = 0; q < 2; q++) bf[g][q] = Wp[q][g * 4];

    const int arow = lane >> 2;
    const int acol = lane & 3;

#pragma unroll
    for (int s = 0; s < 8; s++) {          // K = 8 steps of 16
        const int cur = s % 3;
        unsigned bh[2][2], bl[2][2];
#pragma unroll
        for (int q = 0; q < 2; q++) {
            split2(make_float2(bf[cur][q].x, bf[cur][q].y), bh[q][0], bl[q][0]);
            split2(make_float2(bf[cur][q].z, bf[cur][q].w), bh[q][1], bl[q][1]);
        }
        if (s < 5) {
#pragma unroll
            for (int q = 0; q < 2; q++) bf[cur][q] = Wp[q][(s + 3) * 4];
        }
        unsigned ah[2][4], al[2][4];
#pragma unroll
        for (int mt = 0; mt < 2; mt++) {
            const int base = (mt * 16 + arow) * XS + s * 16 + acol * 4;
            uint2 h0 = *(const uint2*)(xh + base);
            uint2 h1 = *(const uint2*)(xh + base + 8 * XS);
            uint2 l0 = *(const uint2*)(xl + base);
            uint2 l1 = *(const uint2*)(xl + base + 8 * XS);
            ah[mt][0] = h0.x; ah[mt][2] = h0.y;
            ah[mt][1] = h1.x; ah[mt][3] = h1.y;
            al[mt][0] = l0.x; al[mt][2] = l0.y;
            al[mt][1] = l1.x; al[mt][3] = l1.y;
        }
#pragma unroll
        for (int q = 0; q < 2; q++) {
#pragma unroll
            for (int mt = 0; mt < 2; mt++) {
                mma_f16(acc[mt][q], ah[mt][0], ah[mt][1], ah[mt][2], ah[mt][3],
                        bl[q][0], bl[q][1]);
                mma_f16(acc[mt][q], al[mt][0], al[mt][1], al[mt][2], al[mt][3],
                        bh[q][0], bh[q][1]);
                mma_f16(acc[mt][q], ah[mt][0], ah[mt][1], ah[mt][2], ah[mt][3],
                        bh[q][0], bh[q][1]);
            }
        }
    }

    // Epilogue: u_hat int16 (q = round(u*256)); short2 stores, 2 cols contiguous
#pragma unroll
    for (int mt = 0; mt < 2; mt++) {
        int b0r = mt * 16 + (lane >> 2);
#pragma unroll
        for (int q = 0; q < 2; q++) {
            int col = nbase + q * 8 + 2 * (lane & 3);
            short2 s01 = make_short2((short)__float2int_rn(acc[mt][q][0] * QS),
                                     (short)__float2int_rn(acc[mt][q][1] * QS));
            short2 s23 = make_short2((short)__float2int_rn(acc[mt][q][2] * QS),
                                     (short)__float2int_rn(acc[mt][q][3] * QS));
            *(short2*)(g_uhat + ((size_t)b0r * II + i) * JD + col)       = s01;
            *(short2*)(g_uhat + ((size_t)(b0r + 8) * II + i) * JD + col) = s23;
        }
    }
}

// ---------------------------------------------------------------------------
// Kernel 2: partial sums over i of u_hat (route-1: c = 1/J uniform).
// int32 accumulation: BIT-EXACT sum of int16 q-values.
// ---------------------------------------------------------------------------
__global__ void reduce_uhat_kernel() {
    int idx = blockIdx.x * 256 + threadIdx.x;   // 0..8191 = b*256 + g
    int ch  = blockIdx.y;
    int b   = idx >> 8, g = idx & 255;          // g: 8-short group within row
    const uint4* p = (const uint4*)(g_uhat + ((size_t)b * II + ch * ICH_R) * JD) + g;
    int acc[8] = {};
#pragma unroll 8
    for (int k = 0; k < ICH_R; k++) {
        uint4 raw = p[(size_t)k * (JD / 8)];
        unsigned w[4] = {raw.x, raw.y, raw.z, raw.w};
#pragma unroll
        for (int m = 0; m < 4; m++) {
            acc[2 * m]     += (int)((short)(w[m] & 0xFFFFu));
            acc[2 * m + 1] += (int)((short)(w[m] >> 16));
        }
    }
    float* sp = &g_spart[ch][b * JD + g * 8];
    *(float4*)(sp)     = make_float4(acc[0] * QSI, acc[1] * QSI, acc[2] * QSI, acc[3] * QSI);
    *(float4*)(sp + 4) = make_float4(acc[4] * QSI, acc[5] * QSI, acc[6] * QSI, acc[7] * QSI);
}

// ---------------------------------------------------------------------------
// Kernel 3: reduce partials + squash.  out==nullptr -> write g_v.
// ---------------------------------------------------------------------------
__global__ void __launch_bounds__(256)
squash_kernel(float scale, float* out, int nchunk) {
    const int tid  = threadIdx.x;
    const int bjd  = blockIdx.x * 256 + tid;    // global (bj*64 + d)
    const int lane = tid & 31;
    const int warp = tid >> 5;
    const int grp  = tid >> 6;                  // 0..3: (b,j) group in block

    float s = 0.f;
#pragma unroll 8
    for (int ch = 0; ch < nchunk; ch++) s += g_spart[ch][bjd];
    s *= scale;

    float n2 = s * s;
#pragma unroll
    for (int off = 16; off; off >>= 1) n2 += __shfl_xor_sync(0xffffffffu, n2, off);
    __shared__ float tmp[8];
    if (lane == 0) tmp[warp] = n2;
    __syncthreads();
    n2 = tmp[2 * grp] + tmp[2 * grp + 1];

    float norm = sqrtf(n2);
    float f    = norm / (1.f + n2);
    float* dst = out ? out : g_v;
    dst[bjd] = s * f;
}

// ---------------------------------------------------------------------------
// Kernel 4: fused agree + next-route partial-sum, register-resident,
// RAW-RING pipeline depth 3: u kept as undecoded uint4 (3 pair-slots), pair
// p+3's loads issued right after decoding slot p -> 6 LDG.128 in flight per
// thread (vs 2 in r14; route measured MLP-bound at 2.75 TB/s).
// Dual softmax per pair (lanes 0-15: i0, lanes 16-31: i1), one bar per pair.
// Thread t owns (j = t>>3, d = (t&7)*8 .. +7).
// ---------------------------------------------------------------------------
template <bool FIRST>
__global__ void __launch_bounds__(256)
route_kernel() {
    __shared__ float bj_s[4][JJ];

    const int b    = blockIdx.x;
    const int ch   = blockIdx.y;
    const int tid  = threadIdx.x;
    const int lane = tid & 31;
    const int j    = tid >> 3;        // 0..31
    const int d0   = (tid & 7) * 8;
    const int hl   = lane & 15;       // position within 16-lane half

    float v[8];
#pragma unroll
    for (int k = 0; k < 8; k++) v[k] = g_v[b * JD + j * 64 + d0 + k];

    const short* ub = g_uhat + ((size_t)b * II + ch * RICH) * JD + j * 64 + d0;
    const float* bb = g_b1 + ((size_t)b * II + ch * RICH) * JJ + j;
    float* bw       = g_b1 + ((size_t)b * II + ch * RICH) * JJ + j;

    float sacc[8] = {};
    uint4 raw[3][2];     // ring: 3 pair-slots x 2 i's, undecoded
    float b1v[3][2];

    // prologue: load pairs 0, 1, 2 (i = 0..5)
#pragma unroll
    for (int sl = 0; sl < 3; sl++)
#pragma unroll
        for (int r = 0; r < 2; r++) {
            const size_t t = 2 * sl + r;
            raw[sl][r] = *(const uint4*)(ub + t * JD);
            b1v[sl][r] = FIRST ? 0.f : bb[t * JJ];
        }

#pragma unroll
    for (int p = 0; p < RICH / 2; p++) {
        const int slot = p % 3;

        // decode current pair out of the ring (frees the slot)
        float u[2][8];
        float b1c[2];
#pragma unroll
        for (int r = 0; r < 2; r++) {
            unpk(raw[slot][r].x, u[r][0], u[r][1]);
            unpk(raw[slot][r].y, u[r][2], u[r][3]);
            unpk(raw[slot][r].z, u[r][4], u[r][5]);
            unpk(raw[slot][r].w, u[r][6], u[r][7]);
            b1c[r] = b1v[slot][r];
        }

        // issue pair p+3's loads into the freed slot (deep MLP)
        if (p + 3 < RICH / 2) {
#pragma unroll
            for (int r = 0; r < 2; r++) {
                const size_t t = 2 * (p + 3) + r;
                raw[slot][r] = *(const uint4*)(ub + t * JD);
                b1v[slot][r] = FIRST ? 0.f : bb[t * JJ];
            }
        }

        // agreement dots for both i's of this pair
#pragma unroll
        for (int r = 0; r < 2; r++) {
            const int t = 2 * p + r;
            float dot = 0.f;
#pragma unroll
            for (int k = 0; k < 8; k++) dot = fmaf(u[r][k], v[k], dot);
            dot += __shfl_xor_sync(0xffffffffu, dot, 1);
            dot += __shfl_xor_sync(0xffffffffu, dot, 2);
            dot += __shfl_xor_sync(0xffffffffu, dot, 4);
            if ((lane & 7) == 0) {
                if (FIRST) bw[(size_t)t * JJ] = dot;   // b starts at 0
                bj_s[t & 3][j] = dot + b1c[r];
            }
        }
        __syncthreads();

        // dual softmax: half 0 (lanes 0-15) does i=2p, half 1 does i=2p+1
        {
            const int half = lane >> 4;
            const int slot2 = (2 * p + half) & 3;
            float x0 = bj_s[slot2][hl];
            float x1 = bj_s[slot2][hl + 16];
            float m = fmaxf(x0, x1);
#pragma unroll
            for (int off = 8; off; off >>= 1)
                m = fmaxf(m, __shfl_xor_sync(0xffffffffu, m, off));
            float e0 = __expf(x0 - m);
            float e1 = __expf(x1 - m);
            float ss = e0 + e1;
#pragma unroll
            for (int off = 8; off; off >>= 1)
                ss += __shfl_xor_sync(0xffffffffu, ss, off);
            float inv = __frcp_rn(ss);
            float r0 = e0 * inv;     // c for j = hl      (this half's i)
            float r1 = e1 * inv;     // c for j = hl + 16 (this half's i)

            // broadcast: c for (i0, j) lives in lane (j&15); (i1, j) in 16+(j&15)
            int js = j & 15;
            float a0 = __shfl_sync(0xffffffffu, r0, js);
            float a1 = __shfl_sync(0xffffffffu, r1, js);
            float c0 = (j < 16) ? a0 : a1;
            float b0 = __shfl_sync(0xffffffffu, r0, 16 + js);
            float b1x = __shfl_sync(0xffffffffu, r1, 16 + js);
            float c1 = (j < 16) ? b0 : b1x;

#pragma unroll
            for (int k = 0; k < 8; k++) sacc[k] = fmaf(c0, u[0][k], sacc[k]);
#pragma unroll
            for (int k = 0; k < 8; k++) sacc[k] = fmaf(c1, u[1][k], sacc[k]);
        }
    }

    float* sp = &g_spart[ch][b * JD + tid * 8];
    *(float4*)(sp)     = make_float4(sacc[0], sacc[1], sacc[2], sacc[3]);
    *(float4*)(sp + 4) = make_float4(sacc[4], sacc[5], sacc[6], sacc[7]);
}

// ---------------------------------------------------------------------------
extern "C" void kernel_launch(void* const* d_in, const int* in_sizes, int n_in,
                              void* d_out, int out_size) {
    const float *x, *W;
    if (in_sizes[0] == BB * II * CC) { x = (const float*)d_in[0]; W = (const float*)d_in[1]; }
    else                             { x = (const float*)d_in[1]; W = (const float*)d_in[0]; }
    float* out = (float*)d_out;

    // 1) u_hat GEMM (fp16x3 MMA, fp32-accurate, int16 u_hat output)
    gemm_kernel<<<dim3(16, II), 256>>>(x, W);
    // 2) s1 = sum_i u_hat (bit-exact int32 partials), v1 = squash(s1 / J)
    reduce_uhat_kernel<<<dim3(BB * JD / 8 / 256, NCH_R), 256>>>();
    squash_kernel<<<BB * JJ / 4, 256>>>(1.0f / (float)JJ, nullptr, NCH_R);
    // 3) agree1 + route2 partials; v2 = squash(s2)
    route_kernel<true><<<dim3(BB, RCH), 256>>>();
    squash_kernel<<<BB * JJ / 4, 256>>>(1.0f, nullptr, RCH);
    // 4) agree2 + route3 partials; output = squash(s3)
    route_kernel<false><<<dim3(BB, RCH), 256>>>();
    squash_kernel<<<BB * JJ / 4, 256>>>(1.0f, out, RCH);
}

// round 16
// speedup vs baseline: 1.7033x; 1.0230x over previous
#include <cuda_runtime.h>
#include <cuda_fp16.h>
#include <math.h>

#define BB 32
#define II 1024
#define CC 128
#define JJ 32
#define DD 64
#define JD 2048            // JJ*DD
#define NCH_R 32           // reduce chunks (init route)
#define ICH_R (II/NCH_R)   // 32 i's per reduce block
#define RCH 64             // route chunks
#define RICH (II/RCH)      // 16 i's per route block (8 pairs, 4 quads)

#define QS   256.0f        // quantization scale: q = round(u * 256)
#define QSI  (1.0f/256.0f) // decode scale

// Scratch (device globals: no allocation in kernel_launch)
__device__ short g_uhat[(size_t)BB * II * JD];   // int16 q-units, 134 MiB
__device__ float g_spart[RCH][BB * JD];          // partial s sums, fp32
__device__ float g_b1[(size_t)BB * II * JJ];     // routing logits after agree1
__device__ float g_v[BB * JD];                   // current v[b][j][d]

// ---------------------------------------------------------------------------
// fp16 mma helper (m16n8k16, fp32 accumulate)
// ---------------------------------------------------------------------------
__device__ __forceinline__ void mma_f16(float c[4],
                                        unsigned a0, unsigned a1, unsigned a2, unsigned a3,
                                        unsigned b0, unsigned b1) {
    asm volatile(
        "mma.sync.aligned.m16n8k16.row.col.f32.f16.f16.f32 "
        "{%0,%1,%2,%3}, {%4,%5,%6,%7}, {%8,%9}, {%0,%1,%2,%3};"
        : "+f"(c[0]), "+f"(c[1]), "+f"(c[2]), "+f"(c[3])
        : "r"(a0), "r"(a1), "r"(a2), "r"(a3), "r"(b0), "r"(b1));
}

__device__ __forceinline__ unsigned h2u(__half2 h) {
    return *reinterpret_cast<unsigned*>(&h);
}

// split float2 into fp16 hi + fp16 lo (Markidis), packed half2
__device__ __forceinline__ void split2(float2 w, unsigned& hi, unsigned& lo) {
    __half2 h = __floats2half2_rn(w.x, w.y);
    float2 r = make_float2(w.x - __low2float(h), w.y - __high2float(h));
    __half2 l = __floats2half2_rn(r.x, r.y);
    hi = h2u(h); lo = h2u(l);
}

// unpack one uint (2 int16) to two floats in real units (q * QSI)
__device__ __forceinline__ void unpk(unsigned w, float& f0, float& f1) {
    f0 = (float)((short)(w & 0xFFFFu)) * QSI;
    f1 = (float)((short)(w >> 16))     * QSI;
}

// decode a uint4 (8 int16) to 8 floats
__device__ __forceinline__ void decode8(uint4 raw, float u[8]) {
    unpk(raw.x, u[0], u[1]);
    unpk(raw.y, u[2], u[3]);
    unpk(raw.z, u[4], u[5]);
    unpk(raw.w, u[6], u[7]);
}

// ---------------------------------------------------------------------------
// Kernel 1: u_hat GEMM, fp16x3 error-compensated (~fp32 accuracy), int16 out.
// (r11/r14 base — best measured decomposition.)
// ---------------------------------------------------------------------------
#define XS 144   // half-stride per row (72 words = 8 mod 32: conflict-free LDS.64)

__global__ void __launch_bounds__(256, 3)
gemm_kernel(const float* __restrict__ x, const float* __restrict__ W) {
    __shared__ __half xh[32 * XS];
    __shared__ __half xl[32 * XS];

    const int i    = blockIdx.y;
    const int jt   = blockIdx.x;          // 0..15 -> jd base = jt*128
    const int tid  = threadIdx.x;
    const int lane = tid & 31;
    const int warp = tid >> 5;

    // Stage x[:, i, :] split into fp16 hi/lo, row-major [b][c] (physical c order)
    for (int e = tid * 4; e < BB * CC; e += 1024) {
        int b = e >> 7, c = e & 127;
        float4 v = *(const float4*)(x + ((size_t)b * II + i) * CC + c);
        float f[4] = {v.x, v.y, v.z, v.w};
#pragma unroll
        for (int k = 0; k < 4; k++) {
            __half h = __float2half_rn(f[k]);
            xh[b * XS + c + k] = h;
            xl[b * XS + c + k] = __float2half_rn(f[k] - __half2float(h));
        }
    }
    __syncthreads();

    const int nbase = jt * 128 + warp * 16;   // this warp's jd base (16 wide)
    const float4* Wp[2];
#pragma unroll
    for (int q = 0; q < 2; q++) {
        int n = nbase + q * 8 + (lane >> 2);
        int j = n >> 6, d = n & 63;
        Wp[q] = (const float4*)(W + (((size_t)j * II + i) * DD + d) * CC) + (lane & 3);
    }

    float acc[2][2][4] = {};
    float4 bf[3][2];   // depth-3 prefetch: [step mod 3][q]

    // prologue: steps 0, 1, 2
#pragma unroll
    for (int g = 0; g < 3; g++)
#pragma unroll
        for (int q = 0; q < 2; q++) bf[g][q] = Wp[q][g * 4];

    const int arow = lane >> 2;
    const int acol = lane & 3;

#pragma unroll
    for (int s = 0; s < 8; s++) {          // K = 8 steps of 16
        const int cur = s % 3;
        unsigned bh[2][2], bl[2][2];
#pragma unroll
        for (int q = 0; q < 2; q++) {
            split2(make_float2(bf[cur][q].x, bf[cur][q].y), bh[q][0], bl[q][0]);
            split2(make_float2(bf[cur][q].z, bf[cur][q].w), bh[q][1], bl[q][1]);
        }
        if (s < 5) {
#pragma unroll
            for (int q = 0; q < 2; q++) bf[cur][q] = Wp[q][(s + 3) * 4];
        }
        unsigned ah[2][4], al[2][4];
#pragma unroll
        for (int mt = 0; mt < 2; mt++) {
            const int base = (mt * 16 + arow) * XS + s * 16 + acol * 4;
            uint2 h0 = *(const uint2*)(xh + base);
            uint2 h1 = *(const uint2*)(xh + base + 8 * XS);
            uint2 l0 = *(const uint2*)(xl + base);
            uint2 l1 = *(const uint2*)(xl + base + 8 * XS);
            ah[mt][0] = h0.x; ah[mt][2] = h0.y;
            ah[mt][1] = h1.x; ah[mt][3] = h1.y;
            al[mt][0] = l0.x; al[mt][2] = l0.y;
            al[mt][1] = l1.x; al[mt][3] = l1.y;
        }
#pragma unroll
        for (int q = 0; q < 2; q++) {
#pragma unroll
            for (int mt = 0; mt < 2; mt++) {
                mma_f16(acc[mt][q], ah[mt][0], ah[mt][1], ah[mt][2], ah[mt][3],
                        bl[q][0], bl[q][1]);
                mma_f16(acc[mt][q], al[mt][0], al[mt][1], al[mt][2], al[mt][3],
                        bh[q][0], bh[q][1]);
                mma_f16(acc[mt][q], ah[mt][0], ah[mt][1], ah[mt][2], ah[mt][3],
                        bh[q][0], bh[q][1]);
            }
        }
    }

    // Epilogue: u_hat int16 (q = round(u*256)); short2 stores, 2 cols contiguous
#pragma unroll
    for (int mt = 0; mt < 2; mt++) {
        int b0r = mt * 16 + (lane >> 2);
#pragma unroll
        for (int q = 0; q < 2; q++) {
            int col = nbase + q * 8 + 2 * (lane & 3);
            short2 s01 = make_short2((short)__float2int_rn(acc[mt][q][0] * QS),
                                     (short)__float2int_rn(acc[mt][q][1] * QS));
            short2 s23 = make_short2((short)__float2int_rn(acc[mt][q][2] * QS),
                                     (short)__float2int_rn(acc[mt][q][3] * QS));
            *(short2*)(g_uhat + ((size_t)b0r * II + i) * JD + col)       = s01;
            *(short2*)(g_uhat + ((size_t)(b0r + 8) * II + i) * JD + col) = s23;
        }
    }
}

// ---------------------------------------------------------------------------
// Kernel 2: partial sums over i of u_hat (route-1: c = 1/J uniform).
// int32 accumulation: BIT-EXACT sum of int16 q-values.
// ---------------------------------------------------------------------------
__global__ void reduce_uhat_kernel() {
    int idx = blockIdx.x * 256 + threadIdx.x;   // 0..8191 = b*256 + g
    int ch  = blockIdx.y;
    int b   = idx >> 8, g = idx & 255;          // g: 8-short group within row
    const uint4* p = (const uint4*)(g_uhat + ((size_t)b * II + ch * ICH_R) * JD) + g;
    int acc[8] = {};
#pragma unroll 8
    for (int k = 0; k < ICH_R; k++) {
        uint4 raw = p[(size_t)k * (JD / 8)];
        unsigned w[4] = {raw.x, raw.y, raw.z, raw.w};
#pragma unroll
        for (int m = 0; m < 4; m++) {
            acc[2 * m]     += (int)((short)(w[m] & 0xFFFFu));
            acc[2 * m + 1] += (int)((short)(w[m] >> 16));
        }
    }
    float* sp = &g_spart[ch][b * JD + g * 8];
    *(float4*)(sp)     = make_float4(acc[0] * QSI, acc[1] * QSI, acc[2] * QSI, acc[3] * QSI);
    *(float4*)(sp + 4) = make_float4(acc[4] * QSI, acc[5] * QSI, acc[6] * QSI, acc[7] * QSI);
}

// ---------------------------------------------------------------------------
// Kernel 3: reduce partials + squash.  out==nullptr -> write g_v.
// ---------------------------------------------------------------------------
__global__ void __launch_bounds__(256)
squash_kernel(float scale, float* out, int nchunk) {
    const int tid  = threadIdx.x;
    const int bjd  = blockIdx.x * 256 + tid;    // global (bj*64 + d)
    const int lane = tid & 31;
    const int warp = tid >> 5;
    const int grp  = tid >> 6;                  // 0..3: (b,j) group in block

    float s = 0.f;
#pragma unroll 8
    for (int ch = 0; ch < nchunk; ch++) s += g_spart[ch][bjd];
    s *= scale;

    float n2 = s * s;
#pragma unroll
    for (int off = 16; off; off >>= 1) n2 += __shfl_xor_sync(0xffffffffu, n2, off);
    __shared__ float tmp[8];
    if (lane == 0) tmp[warp] = n2;
    __syncthreads();
    n2 = tmp[2 * grp] + tmp[2 * grp + 1];

    float norm = sqrtf(n2);
    float f    = norm / (1.f + n2);
    float* dst = out ? out : g_v;
    dst[bjd] = s * f;
}

// ---------------------------------------------------------------------------
// Kernel 4: fused agree + next-route partial-sum, register-resident.
// QUAD processing: 2 pairs (4 i's) per barrier -> 4 barriers per block (was 8).
// Raw ring of 4 pair-slots (8 LDG.128 in flight at prologue); accumulation
// RE-DECODES from the undecoded ring after softmax (keeps regs low); two
// independent dual-softmax chains per quad (ILP overlaps shuffle latency).
// 8 logit slots (quad-parity x 4) for WAR safety with one barrier per quad.
// Thread t owns (j = t>>3, d = (t&7)*8 .. +7).
// ---------------------------------------------------------------------------
template <bool FIRST>
__global__ void __launch_bounds__(256, 3)
route_kernel() {
    __shared__ float bj_s[8][JJ];

    const int b    = blockIdx.x;
    const int ch   = blockIdx.y;
    const int tid  = threadIdx.x;
    const int lane = tid & 31;
    const int j    = tid >> 3;        // 0..31
    const int d0   = (tid & 7) * 8;
    const int hl   = lane & 15;       // position within 16-lane half
    const int half = lane >> 4;
    const int js   = j & 15;

    float v[8];
#pragma unroll
    for (int k = 0; k < 8; k++) v[k] = g_v[b * JD + j * 64 + d0 + k];

    const short* ub = g_uhat + ((size_t)b * II + ch * RICH) * JD + j * 64 + d0;
    const float* bb = g_b1 + ((size_t)b * II + ch * RICH) * JJ + j;
    float* bw       = g_b1 + ((size_t)b * II + ch * RICH) * JJ + j;

    float sacc[8] = {};
    uint4 raw[4][2];     // ring: 4 pair-slots x 2 i's, undecoded
    float b1v[4][2];

    // prologue: load pairs 0..3 (i = 0..7): 8 LDG.128 in flight
#pragma unroll
    for (int sl = 0; sl < 4; sl++)
#pragma unroll
        for (int r = 0; r < 2; r++) {
            const size_t t = 2 * sl + r;
            raw[sl][r] = *(const uint4*)(ub + t * JD);
            b1v[sl][r] = FIRST ? 0.f : bb[t * JJ];
        }

#pragma unroll
    for (int q = 0; q < RICH / 4; q++) {     // 4 quads
        const int s0 = (2 * q) & 3;          // slot of pair A
        const int s1 = (2 * q + 1) & 3;      // slot of pair B
        const int lbase = (q & 1) * 4;       // logit slot base (WAR safety)

        // dots for 4 i's (decode transiently; ring keeps raw for re-decode)
#pragma unroll
        for (int r = 0; r < 4; r++) {
            const int sl = (r < 2) ? s0 : s1;
            const int rr = r & 1;
            float u[8];
            decode8(raw[sl][rr], u);
            float dot = 0.f;
#pragma unroll
            for (int k = 0; k < 8; k++) dot = fmaf(u[k], v[k], dot);
            dot += __shfl_xor_sync(0xffffffffu, dot, 1);
            dot += __shfl_xor_sync(0xffffffffu, dot, 2);
            dot += __shfl_xor_sync(0xffffffffu, dot, 4);
            if ((lane & 7) == 0) {
                const size_t t = 4 * q + r;
                if (FIRST) bw[t * JJ] = dot;     // b starts at 0
                bj_s[lbase + r][j] = dot + b1v[sl][rr];
            }
        }
        __syncthreads();

        // two dual-softmax chains (independent -> ILP)
        float c[4];
#pragma unroll
        for (int cp = 0; cp < 2; cp++) {
            const int slot2 = lbase + cp * 2 + half;   // this half's i
            float x0 = bj_s[slot2][hl];
            float x1 = bj_s[slot2][hl + 16];
            float m = fmaxf(x0, x1);
#pragma unroll
            for (int off = 8; off; off >>= 1)
                m = fmaxf(m, __shfl_xor_sync(0xffffffffu, m, off));
            float e0 = __expf(x0 - m);
            float e1 = __expf(x1 - m);
            float ss = e0 + e1;
#pragma unroll
            for (int off = 8; off; off >>= 1)
                ss += __shfl_xor_sync(0xffffffffu, ss, off);
            float inv = __frcp_rn(ss);
            float r0 = e0 * inv;     // c for j = hl      (this half's i)
            float r1 = e1 * inv;     // c for j = hl + 16 (this half's i)

            float a0 = __shfl_sync(0xffffffffu, r0, js);
            float a1 = __shfl_sync(0xffffffffu, r1, js);
            c[2 * cp]     = (j < 16) ? a0 : a1;
            float b0 = __shfl_sync(0xffffffffu, r0, 16 + js);
            float b1x = __shfl_sync(0xffffffffu, r1, 16 + js);
            c[2 * cp + 1] = (j < 16) ? b0 : b1x;
        }

        // accumulate: re-decode from the ring
#pragma unroll
        for (int r = 0; r < 4; r++) {
            const int sl = (r < 2) ? s0 : s1;
            const int rr = r & 1;
            float u[8];
            decode8(raw[sl][rr], u);
#pragma unroll
            for (int k = 0; k < 8; k++) sacc[k] = fmaf(c[r], u[k], sacc[k]);
        }

        // prefetch pairs 2q+4, 2q+5 into the freed slots
        if (q < RICH / 4 - 2) {
#pragma unroll
            for (int pr = 0; pr < 2; pr++) {
                const int pn = 2 * q + 4 + pr;
                const int sl = pn & 3;
#pragma unroll
                for (int rr = 0; rr < 2; rr++) {
                    const size_t t = 2 * pn + rr;
                    raw[sl][rr] = *(const uint4*)(ub + t * JD);
                    b1v[sl][rr] = FIRST ? 0.f : bb[t * JJ];
                }
            }
        }
    }

    float* sp = &g_spart[ch][b * JD + tid * 8];
    *(float4*)(sp)     = make_float4(sacc[0], sacc[1], sacc[2], sacc[3]);
    *(float4*)(sp + 4) = make_float4(sacc[4], sacc[5], sacc[6], sacc[7]);
}

// ---------------------------------------------------------------------------
extern "C" void kernel_launch(void* const* d_in, const int* in_sizes, int n_in,
                              void* d_out, int out_size) {
    const float *x, *W;
    if (in_sizes[0] == BB * II * CC) { x = (const float*)d_in[0]; W = (const float*)d_in[1]; }
    else                             { x = (const float*)d_in[1]; W = (const float*)d_in[0]; }
    float* out = (float*)d_out;

    // 1) u_hat GEMM (fp16x3 MMA, fp32-accurate, int16 u_hat output)
    gemm_kernel<<<dim3(16, II), 256>>>(x, W);
    // 2) s1 = sum_i u_hat (bit-exact int32 partials), v1 = squash(s1 / J)
    reduce_uhat_kernel<<<dim3(BB * JD / 8 / 256, NCH_R), 256>>>();
    squash_kernel<<<BB * JJ / 4, 256>>>(1.0f / (float)JJ, nullptr, NCH_R);
    // 3) agree1 + route2 partials; v2 = squash(s2)
    route_kernel<true><<<dim3(BB, RCH), 256>>>();
    squash_kernel<<<BB * JJ / 4, 256>>>(1.0f, nullptr, RCH);
    // 4) agree2 + route3 partials; output = squash(s3)
    route_kernel<false><<<dim3(BB, RCH), 256>>>();
    squash_kernel<<<BB * JJ / 4, 256>>>(1.0f, out, RCH);
}

// round 17
// speedup vs baseline: 1.7432x; 1.0234x over previous
#include <cuda_runtime.h>
#include <cuda_fp16.h>
#include <math.h>

#define BB 32
#define II 1024
#define CC 128
#define JJ 32
#define DD 64
#define JD 2048            // JJ*DD
#define NCH_R 32           // reduce chunks (init route)
#define ICH_R (II/NCH_R)   // 32 i's per reduce block
#define RCH 64             // route chunks
#define RICH (II/RCH)      // 16 i's per route block (8 pairs, 4 quads)

#define QS   256.0f        // quantization scale: q = round(u * 256)
#define QSI  (1.0f/256.0f) // decode scale

// Scratch (device globals: no allocation in kernel_launch)
__device__ short g_uhat[(size_t)BB * II * JD];   // int16 q-units, 134 MiB
__device__ float g_spart[RCH][BB * JD];          // partial s sums, fp32
__device__ float g_v[BB * JD];                   // accumulated v (v1, then v1+v2)

// ---------------------------------------------------------------------------
// fp16 mma helper (m16n8k16, fp32 accumulate)
// ---------------------------------------------------------------------------
__device__ __forceinline__ void mma_f16(float c[4],
                                        unsigned a0, unsigned a1, unsigned a2, unsigned a3,
                                        unsigned b0, unsigned b1) {
    asm volatile(
        "mma.sync.aligned.m16n8k16.row.col.f32.f16.f16.f32 "
        "{%0,%1,%2,%3}, {%4,%5,%6,%7}, {%8,%9}, {%0,%1,%2,%3};"
        : "+f"(c[0]), "+f"(c[1]), "+f"(c[2]), "+f"(c[3])
        : "r"(a0), "r"(a1), "r"(a2), "r"(a3), "r"(b0), "r"(b1));
}

__device__ __forceinline__ unsigned h2u(__half2 h) {
    return *reinterpret_cast<unsigned*>(&h);
}

// split float2 into fp16 hi + fp16 lo (Markidis), packed half2
__device__ __forceinline__ void split2(float2 w, unsigned& hi, unsigned& lo) {
    __half2 h = __floats2half2_rn(w.x, w.y);
    float2 r = make_float2(w.x - __low2float(h), w.y - __high2float(h));
    __half2 l = __floats2half2_rn(r.x, r.y);
    hi = h2u(h); lo = h2u(l);
}

// decode a uint4 (8 int16) to 8 floats in Q-UNITS (no scaling: pure I2F)
__device__ __forceinline__ void decode8q(uint4 raw, float u[8]) {
    u[0] = (float)((short)(raw.x & 0xFFFFu)); u[1] = (float)((short)(raw.x >> 16));
    u[2] = (float)((short)(raw.y & 0xFFFFu)); u[3] = (float)((short)(raw.y >> 16));
    u[4] = (float)((short)(raw.z & 0xFFFFu)); u[5] = (float)((short)(raw.z >> 16));
    u[6] = (float)((short)(raw.w & 0xFFFFu)); u[7] = (float)((short)(raw.w >> 16));
}

// ---------------------------------------------------------------------------
// Kernel 1: u_hat GEMM, fp16x3 error-compensated (~fp32 accuracy), int16 out.
// (r11/r14 base — best measured decomposition.)
// ---------------------------------------------------------------------------
#define XS 144   // half-stride per row (72 words = 8 mod 32: conflict-free LDS.64)

__global__ void __launch_bounds__(256, 3)
gemm_kernel(const float* __restrict__ x, const float* __restrict__ W) {
    __shared__ __half xh[32 * XS];
    __shared__ __half xl[32 * XS];

    const int i    = blockIdx.y;
    const int jt   = blockIdx.x;          // 0..15 -> jd base = jt*128
    const int tid  = threadIdx.x;
    const int lane = tid & 31;
    const int warp = tid >> 5;

    // Stage x[:, i, :] split into fp16 hi/lo, row-major [b][c] (physical c order)
    for (int e = tid * 4; e < BB * CC; e += 1024) {
        int b = e >> 7, c = e & 127;
        float4 v = *(const float4*)(x + ((size_t)b * II + i) * CC + c);
        float f[4] = {v.x, v.y, v.z, v.w};
#pragma unroll
        for (int k = 0; k < 4; k++) {
            __half h = __float2half_rn(f[k]);
            xh[b * XS + c + k] = h;
            xl[b * XS + c + k] = __float2half_rn(f[k] - __half2float(h));
        }
    }
    __syncthreads();

    const int nbase = jt * 128 + warp * 16;   // this warp's jd base (16 wide)
    const float4* Wp[2];
#pragma unroll
    for (int q = 0; q < 2; q++) {
        int n = nbase + q * 8 + (lane >> 2);
        int j = n >> 6, d = n & 63;
        Wp[q] = (const float4*)(W + (((size_t)j * II + i) * DD + d) * CC) + (lane & 3);
    }

    float acc[2][2][4] = {};
    float4 bf[3][2];   // depth-3 prefetch: [step mod 3][q]

    // prologue: steps 0, 1, 2
#pragma unroll
    for (int g = 0; g < 3; g++)
#pragma unroll
        for (int q = 0; q < 2; q++) bf[g][q] = Wp[q][g * 4];

    const int arow = lane >> 2;
    const int acol = lane & 3;

#pragma unroll
    for (int s = 0; s < 8; s++) {          // K = 8 steps of 16
        const int cur = s % 3;
        unsigned bh[2][2], bl[2][2];
#pragma unroll
        for (int q = 0; q < 2; q++) {
            split2(make_float2(bf[cur][q].x, bf[cur][q].y), bh[q][0], bl[q][0]);
            split2(make_float2(bf[cur][q].z, bf[cur][q].w), bh[q][1], bl[q][1]);
        }
        if (s < 5) {
#pragma unroll
            for (int q = 0; q < 2; q++) bf[cur][q] = Wp[q][(s + 3) * 4];
        }
        unsigned ah[2][4], al[2][4];
#pragma unroll
        for (int mt = 0; mt < 2; mt++) {
            const int base = (mt * 16 + arow) * XS + s * 16 + acol * 4;
            uint2 h0 = *(const uint2*)(xh + base);
            uint2 h1 = *(const uint2*)(xh + base + 8 * XS);
            uint2 l0 = *(const uint2*)(xl + base);
            uint2 l1 = *(const uint2*)(xl + base + 8 * XS);
            ah[mt][0] = h0.x; ah[mt][2] = h0.y;
            ah[mt][1] = h1.x; ah[mt][3] = h1.y;
            al[mt][0] = l0.x; al[mt][2] = l0.y;
            al[mt][1] = l1.x; al[mt][3] = l1.y;
        }
#pragma unroll
        for (int q = 0; q < 2; q++) {
#pragma unroll
            for (int mt = 0; mt < 2; mt++) {
                mma_f16(acc[mt][q], ah[mt][0], ah[mt][1], ah[mt][2], ah[mt][3],
                        bl[q][0], bl[q][1]);
                mma_f16(acc[mt][q], al[mt][0], al[mt][1], al[mt][2], al[mt][3],
                        bh[q][0], bh[q][1]);
                mma_f16(acc[mt][q], ah[mt][0], ah[mt][1], ah[mt][2], ah[mt][3],
                        bh[q][0], bh[q][1]);
            }
        }
    }

    // Epilogue: u_hat int16 (q = round(u*256)); short2 stores, 2 cols contiguous
#pragma unroll
    for (int mt = 0; mt < 2; mt++) {
        int b0r = mt * 16 + (lane >> 2);
#pragma unroll
        for (int q = 0; q < 2; q++) {
            int col = nbase + q * 8 + 2 * (lane & 3);
            short2 s01 = make_short2((short)__float2int_rn(acc[mt][q][0] * QS),
                                     (short)__float2int_rn(acc[mt][q][1] * QS));
            short2 s23 = make_short2((short)__float2int_rn(acc[mt][q][2] * QS),
                                     (short)__float2int_rn(acc[mt][q][3] * QS));
            *(short2*)(g_uhat + ((size_t)b0r * II + i) * JD + col)       = s01;
            *(short2*)(g_uhat + ((size_t)(b0r + 8) * II + i) * JD + col) = s23;
        }
    }
}

// ---------------------------------------------------------------------------
// Kernel 2: partial sums over i of u_hat (route-1: c = 1/J uniform).
// int32 accumulation: BIT-EXACT sum of int16 q-values.
// ---------------------------------------------------------------------------
__global__ void reduce_uhat_kernel() {
    int idx = blockIdx.x * 256 + threadIdx.x;   // 0..8191 = b*256 + g
    int ch  = blockIdx.y;
    int b   = idx >> 8, g = idx & 255;          // g: 8-short group within row
    const uint4* p = (const uint4*)(g_uhat + ((size_t)b * II + ch * ICH_R) * JD) + g;
    int acc[8] = {};
#pragma unroll 8
    for (int k = 0; k < ICH_R; k++) {
        uint4 raw = p[(size_t)k * (JD / 8)];
        unsigned w[4] = {raw.x, raw.y, raw.z, raw.w};
#pragma unroll
        for (int m = 0; m < 4; m++) {
            acc[2 * m]     += (int)((short)(w[m] & 0xFFFFu));
            acc[2 * m + 1] += (int)((short)(w[m] >> 16));
        }
    }
    float* sp = &g_spart[ch][b * JD + g * 8];
    *(float4*)(sp)     = make_float4(acc[0] * QSI, acc[1] * QSI, acc[2] * QSI, acc[3] * QSI);
    *(float4*)(sp + 4) = make_float4(acc[4] * QSI, acc[5] * QSI, acc[6] * QSI, acc[7] * QSI);
}

// ---------------------------------------------------------------------------
// Kernel 3: reduce partials + squash.
// accum=0: dst = squash(s)            (dst = g_v or out)
// accum=1: g_v += squash(s)           (builds v1+v2 for the logit identity)
// ---------------------------------------------------------------------------
__global__ void __launch_bounds__(256)
squash_kernel(float scale, float* out, int nchunk, int accum) {
    const int tid  = threadIdx.x;
    const int bjd  = blockIdx.x * 256 + tid;    // global (bj*64 + d)
    const int lane = tid & 31;
    const int warp = tid >> 5;
    const int grp  = tid >> 6;                  // 0..3: (b,j) group in block

    float s = 0.f;
#pragma unroll 8
    for (int ch = 0; ch < nchunk; ch++) s += g_spart[ch][bjd];
    s *= scale;

    float n2 = s * s;
#pragma unroll
    for (int off = 16; off; off >>= 1) n2 += __shfl_xor_sync(0xffffffffu, n2, off);
    __shared__ float tmp[8];
    if (lane == 0) tmp[warp] = n2;
    __syncthreads();
    n2 = tmp[2 * grp] + tmp[2 * grp + 1];

    float norm = sqrtf(n2);
    float f    = norm / (1.f + n2);
    float val  = s * f;
    if (accum) g_v[bjd] += val;
    else {
        float* dst = out ? out : g_v;
        dst[bjd] = val;
    }
}

// ---------------------------------------------------------------------------
// Kernel 4: fused agree + next-route partial-sum. NO b1 state: logits are
// linear in v, so pass 2 dots u against the ACCUMULATED v (v1+v2) — the
// stored-b1 path is algebraically identical and is gone entirely.
// QSI folded out of inner loops: v pre-scaled by QSI (dot in real units);
// softmax reciprocal pre-scaled by QSI (c arrives ready for q-unit accum).
// QUAD processing (4 i's / barrier), raw ring of 4 pair-slots, re-decode
// for accumulation (pure I2F now). Thread t owns (j=t>>3, d=(t&7)*8..+7).
// ---------------------------------------------------------------------------
__global__ void __launch_bounds__(256, 3)
route_kernel() {
    __shared__ float bj_s[8][JJ];

    const int b    = blockIdx.x;
    const int ch   = blockIdx.y;
    const int tid  = threadIdx.x;
    const int lane = tid & 31;
    const int j    = tid >> 3;        // 0..31
    const int d0   = (tid & 7) * 8;
    const int hl   = lane & 15;       // position within 16-lane half
    const int half = lane >> 4;
    const int js   = j & 15;

    float v[8];                       // pre-scaled by QSI: dot(qf, v) = real logit
#pragma unroll
    for (int k = 0; k < 8; k++) v[k] = g_v[b * JD + j * 64 + d0 + k] * QSI;

    const short* ub = g_uhat + ((size_t)b * II + ch * RICH) * JD + j * 64 + d0;

    float sacc[8] = {};               // real units (c pre-scaled by QSI)
    uint4 raw[4][2];                  // ring: 4 pair-slots x 2 i's, undecoded

    // prologue: load pairs 0..3 (i = 0..7): 8 LDG.128 in flight
#pragma unroll
    for (int sl = 0; sl < 4; sl++)
#pragma unroll
        for (int r = 0; r < 2; r++)
            raw[sl][r] = *(const uint4*)(ub + (size_t)(2 * sl + r) * JD);

#pragma unroll
    for (int q = 0; q < RICH / 4; q++) {     // 4 quads
        const int s0 = (2 * q) & 3;          // slot of pair A
        const int s1 = (2 * q + 1) & 3;      // slot of pair B
        const int lbase = (q & 1) * 4;       // logit slot base (WAR safety)

        // dots for 4 i's (decode transiently in q-units; ring keeps raw)
#pragma unroll
        for (int r = 0; r < 4; r++) {
            const int sl = (r < 2) ? s0 : s1;
            const int rr = r & 1;
            float u[8];
            decode8q(raw[sl][rr], u);
            float dot = 0.f;
#pragma unroll
            for (int k = 0; k < 8; k++) dot = fmaf(u[k], v[k], dot);
            dot += __shfl_xor_sync(0xffffffffu, dot, 1);
            dot += __shfl_xor_sync(0xffffffffu, dot, 2);
            dot += __shfl_xor_sync(0xffffffffu, dot, 4);
            if ((lane & 7) == 0) bj_s[lbase + r][j] = dot;
        }
        __syncthreads();

        // two dual-softmax chains (independent -> ILP); c pre-scaled by QSI
        float c[4];
#pragma unroll
        for (int cp = 0; cp < 2; cp++) {
            const int slot2 = lbase + cp * 2 + half;   // this half's i
            float x0 = bj_s[slot2][hl];
            float x1 = bj_s[slot2][hl + 16];
            float m = fmaxf(x0, x1);
#pragma unroll
            for (int off = 8; off; off >>= 1)
                m = fmaxf(m, __shfl_xor_sync(0xffffffffu, m, off));
            float e0 = __expf(x0 - m);
            float e1 = __expf(x1 - m);
            float ss = e0 + e1;
#pragma unroll
            for (int off = 8; off; off >>= 1)
                ss += __shfl_xor_sync(0xffffffffu, ss, off);
            float inv = __frcp_rn(ss) * QSI;   // fold decode scale into c
            float r0 = e0 * inv;     // c·QSI for j = hl      (this half's i)
            float r1 = e1 * inv;     // c·QSI for j = hl + 16 (this half's i)

            float a0 = __shfl_sync(0xffffffffu, r0, js);
            float a1 = __shfl_sync(0xffffffffu, r1, js);
            c[2 * cp]     = (j < 16) ? a0 : a1;
            float b0 = __shfl_sync(0xffffffffu, r0, 16 + js);
            float b1x = __shfl_sync(0xffffffffu, r1, 16 + js);
            c[2 * cp + 1] = (j < 16) ? b0 : b1x;
        }

        // accumulate: re-decode from the ring (pure I2F)
#pragma unroll
        for (int r = 0; r < 4; r++) {
            const int sl = (r < 2) ? s0 : s1;
            const int rr = r & 1;
            float u[8];
            decode8q(raw[sl][rr], u);
#pragma unroll
            for (int k = 0; k < 8; k++) sacc[k] = fmaf(c[r], u[k], sacc[k]);
        }

        // prefetch pairs 2q+4, 2q+5 into the freed slots
        if (q < RICH / 4 - 2) {
#pragma unroll
            for (int pr = 0; pr < 2; pr++) {
                const int pn = 2 * q + 4 + pr;
                const int sl = pn & 3;
#pragma unroll
                for (int rr = 0; rr < 2; rr++)
                    raw[sl][rr] = *(const uint4*)(ub + (size_t)(2 * pn + rr) * JD);
            }
        }
    }

    float* sp = &g_spart[ch][b * JD + tid * 8];
    *(float4*)(sp)     = make_float4(sacc[0], sacc[1], sacc[2], sacc[3]);
    *(float4*)(sp + 4) = make_float4(sacc[4], sacc[5], sacc[6], sacc[7]);
}

// ---------------------------------------------------------------------------
extern "C" void kernel_launch(void* const* d_in, const int* in_sizes, int n_in,
                              void* d_out, int out_size) {
    const float *x, *W;
    if (in_sizes[0] == BB * II * CC) { x = (const float*)d_in[0]; W = (const float*)d_in[1]; }
    else                             { x = (const float*)d_in[1]; W = (const float*)d_in[0]; }
    float* out = (float*)d_out;

    // 1) u_hat GEMM (fp16x3 MMA, fp32-accurate, int16 u_hat output)
    gemm_kernel<<<dim3(16, II), 256>>>(x, W);
    // 2) s1 = sum_i u_hat (bit-exact int32 partials), v1 = squash(s1 / J)
    reduce_uhat_kernel<<<dim3(BB * JD / 8 / 256, NCH_R), 256>>>();
    squash_kernel<<<BB * JJ / 4, 256>>>(1.0f / (float)JJ, nullptr, NCH_R, 0);
    // 3) route pass 2 (logits = u.v1); g_v += v2  (b-linearity identity)
    route_kernel<<<dim3(BB, RCH), 256>>>();
    squash_kernel<<<BB * JJ / 4, 256>>>(1.0f, nullptr, RCH, 1);
    // 4) route pass 3 (logits = u.(v1+v2)); output = squash(s3)
    route_kernel<<<dim3(BB, RCH), 256>>>();
    squash_kernel<<<BB * JJ / 4, 256>>>(1.0f, out, RCH, 0);
}